// round 1
// baseline (speedup 1.0000x reference)
#include <cuda_runtime.h>
#include <cuda_bf16.h>
#include <cstdint>
#include <cstdio>

// Problem constants
#define SEQ     2048
#define BATCH   16
#define DMODEL  512
#define FFDIM   2048
#define MTOT    (SEQ*BATCH)          // 32768 token rows
#define CH      (BATCH*DMODEL)       // 8192 channels for the scan
#define ALPHA_F 0.9f
#define EPS_F   1e-5f

// Scan chunking
#define NCHUNK  16
#define CLEN    (SEQ/NCHUNK)         // 128

// ---------------- scratch (static device globals; no allocation) ------------
__device__ float g_y [(size_t)MTOT*DMODEL];   // LN output (reused for y1,y2)
__device__ float g_z [(size_t)MTOT*DMODEL];   // projection output
__device__ float g_x1[(size_t)MTOT*DMODEL];   // x + attn
__device__ float g_h [(size_t)MTOT*FFDIM];    // relu(ffn hidden)
__device__ float g_E [NCHUNK*CH];             // chunk-local scan end values
__device__ float g_carry[NCHUNK*CH];          // inter-chunk carries

// ---------------- helpers ----------------------------------------------------
__device__ __forceinline__ uint32_t f2tf32(float f) {
    uint32_t u;
    asm("cvt.rna.tf32.f32 %0, %1;" : "=r"(u) : "f"(f));
    return u;
}

__device__ __forceinline__ void mma_tf32(float* c, const uint32_t* a, const uint32_t* b) {
    asm volatile(
        "mma.sync.aligned.m16n8k8.row.col.f32.tf32.tf32.f32 "
        "{%0,%1,%2,%3},{%4,%5,%6,%7},{%8,%9},{%0,%1,%2,%3};\n"
        : "+f"(c[0]), "+f"(c[1]), "+f"(c[2]), "+f"(c[3])
        : "r"(a[0]), "r"(a[1]), "r"(a[2]), "r"(a[3]),
          "r"(b[0]), "r"(b[1]));
}

// ---------------- LayerNorm: one warp per row of 512 -------------------------
__global__ __launch_bounds__(256) void ln_kernel(
    const float* __restrict__ x, const float* __restrict__ gamma,
    const float* __restrict__ beta, float* __restrict__ y)
{
    int row  = blockIdx.x * 8 + (threadIdx.x >> 5);
    int lane = threadIdx.x & 31;
    const float4* xr = reinterpret_cast<const float4*>(x + (size_t)row * DMODEL);
    const float4* g4 = reinterpret_cast<const float4*>(gamma);
    const float4* b4 = reinterpret_cast<const float4*>(beta);
    float4* yr = reinterpret_cast<float4*>(y + (size_t)row * DMODEL);

    float4 v[4];
    float sum = 0.f, sq = 0.f;
#pragma unroll
    for (int i = 0; i < 4; i++) {
        v[i] = xr[lane + i * 32];
        sum += v[i].x + v[i].y + v[i].z + v[i].w;
        sq  += v[i].x*v[i].x + v[i].y*v[i].y + v[i].z*v[i].z + v[i].w*v[i].w;
    }
#pragma unroll
    for (int o = 16; o; o >>= 1) {
        sum += __shfl_xor_sync(0xffffffffu, sum, o);
        sq  += __shfl_xor_sync(0xffffffffu, sq,  o);
    }
    float m    = sum * (1.f / DMODEL);
    float var  = sq * (1.f / DMODEL) - m * m;
    float rstd = rsqrtf(var + EPS_F);
#pragma unroll
    for (int i = 0; i < 4; i++) {
        float4 gv = g4[lane + i * 32];
        float4 bv = b4[lane + i * 32];
        float4 o;
        o.x = (v[i].x - m) * rstd * gv.x + bv.x;
        o.y = (v[i].y - m) * rstd * gv.y + bv.y;
        o.z = (v[i].z - m) * rstd * gv.z + bv.z;
        o.w = (v[i].w - m) * rstd * gv.w + bv.w;
        yr[lane + i * 32] = o;
    }
}

// ---------------- tf32 tensor-core GEMM: C = act(A*B^T + bias) [+ res] -------
// A: [M,K] row-major fp32.  B: [N,K] row-major fp32 (so C = A*B^T).
// Tiles: BM=128, BN=64, BK=32. 256 threads = 8 warps (4 m x 2 n), warp = 32x32.
#define BM 128
#define BN 64
#define BK 32
#define SPAD 4

template<bool RELU, bool RES>
__global__ __launch_bounds__(256) void gemm_tf32(
    const float* __restrict__ A, const float* __restrict__ B,
    const float* __restrict__ bias, const float* __restrict__ res,
    float* __restrict__ C, int M, int N, int K)
{
    __shared__ uint32_t As[BM][BK + SPAD];
    __shared__ uint32_t Bs[BN][BK + SPAD];

    const int tid  = threadIdx.x;
    const int warp = tid >> 5;
    const int lane = tid & 31;
    const int wm   = warp >> 1;    // 0..3
    const int wn   = warp & 1;     // 0..1
    const int g    = lane >> 2;    // 0..7
    const int tg   = lane & 3;     // 0..3

    const int m0 = blockIdx.y * BM;
    const int n0 = blockIdx.x * BN;

    const int lr = tid >> 3;        // load row base (0..31)
    const int lc = (tid & 7) * 4;   // load col within BK

    float acc[2][4][4];
#pragma unroll
    for (int mt = 0; mt < 2; mt++)
#pragma unroll
        for (int nt = 0; nt < 4; nt++)
#pragma unroll
            for (int i = 0; i < 4; i++) acc[mt][nt][i] = 0.f;

    for (int k0 = 0; k0 < K; k0 += BK) {
#pragma unroll
        for (int r = lr; r < BM; r += 32) {
            float4 v = *reinterpret_cast<const float4*>(&A[(size_t)(m0 + r) * K + k0 + lc]);
            uint4 u = make_uint4(f2tf32(v.x), f2tf32(v.y), f2tf32(v.z), f2tf32(v.w));
            *reinterpret_cast<uint4*>(&As[r][lc]) = u;
        }
#pragma unroll
        for (int r = lr; r < BN; r += 32) {
            float4 v = *reinterpret_cast<const float4*>(&B[(size_t)(n0 + r) * K + k0 + lc]);
            uint4 u = make_uint4(f2tf32(v.x), f2tf32(v.y), f2tf32(v.z), f2tf32(v.w));
            *reinterpret_cast<uint4*>(&Bs[r][lc]) = u;
        }
        __syncthreads();

#pragma unroll
        for (int kk = 0; kk < 4; kk++) {
            uint32_t af[2][4], bf[4][2];
#pragma unroll
            for (int mt = 0; mt < 2; mt++) {
                int mr = wm * 32 + mt * 16;
                af[mt][0] = As[mr + g    ][kk * 8 + tg    ];
                af[mt][1] = As[mr + g + 8][kk * 8 + tg    ];
                af[mt][2] = As[mr + g    ][kk * 8 + tg + 4];
                af[mt][3] = As[mr + g + 8][kk * 8 + tg + 4];
            }
#pragma unroll
            for (int nt = 0; nt < 4; nt++) {
                int nr = wn * 32 + nt * 8;
                bf[nt][0] = Bs[nr + g][kk * 8 + tg    ];
                bf[nt][1] = Bs[nr + g][kk * 8 + tg + 4];
            }
#pragma unroll
            for (int mt = 0; mt < 2; mt++)
#pragma unroll
                for (int nt = 0; nt < 4; nt++)
                    mma_tf32(acc[mt][nt], af[mt], bf[nt]);
        }
        __syncthreads();
    }

    // epilogue: bias (+relu) (+residual)
#pragma unroll
    for (int mt = 0; mt < 2; mt++) {
        int r0 = m0 + wm * 32 + mt * 16 + g;
#pragma unroll
        for (int nt = 0; nt < 4; nt++) {
            int cc = n0 + wn * 32 + nt * 8 + tg * 2;
            float bv0 = bias[cc], bv1 = bias[cc + 1];
            float v0 = acc[mt][nt][0] + bv0;
            float v1 = acc[mt][nt][1] + bv1;
            float v2 = acc[mt][nt][2] + bv0;
            float v3 = acc[mt][nt][3] + bv1;
            if (RELU) {
                v0 = fmaxf(v0, 0.f); v1 = fmaxf(v1, 0.f);
                v2 = fmaxf(v2, 0.f); v3 = fmaxf(v3, 0.f);
            }
            if (RES) {
                const float* r1 = res + (size_t)r0 * N + cc;
                const float* r2 = res + (size_t)(r0 + 8) * N + cc;
                v0 += r1[0]; v1 += r1[1];
                v2 += r2[0]; v3 += r2[1];
            }
            float2 o0 = make_float2(v0, v1);
            float2 o1 = make_float2(v2, v3);
            *reinterpret_cast<float2*>(&C[(size_t)r0 * N + cc])       = o0;
            *reinterpret_cast<float2*>(&C[(size_t)(r0 + 8) * N + cc]) = o1;
        }
    }
}

// ---------------- causal exp-decay mixing as a chunked linear scan -----------
// attn_i = P_i + (1 - S_{i+1}) z_i,  P_i = a(P_{i-1} + z_i),  S_{i+1}=sum_{k=1}^{i+1} a^k
__global__ __launch_bounds__(256) void scan_pass1(const float* __restrict__ z)
{
    int ch    = blockIdx.x * 256 + threadIdx.x;   // 0..CH-1
    int chunk = blockIdx.y;
    const float* zp = z + (size_t)chunk * CLEN * CH + ch;
    float P = 0.f;
#pragma unroll 4
    for (int t = 0; t < CLEN; t++)
        P = ALPHA_F * (P + zp[(size_t)t * CH]);
    g_E[chunk * CH + ch] = P;
}

__global__ __launch_bounds__(256) void scan_pass2()
{
    int ch = blockIdx.x * 256 + threadIdx.x;
    float aL = powf(ALPHA_F, (float)CLEN);
    float carry = 0.f;
#pragma unroll
    for (int c = 0; c < NCHUNK; c++) {
        g_carry[c * CH + ch] = carry;
        carry = g_E[c * CH + ch] + aL * carry;
    }
}

__global__ __launch_bounds__(256) void scan_pass3(
    const float* __restrict__ x, const float* __restrict__ z, float* __restrict__ x1)
{
    int ch    = blockIdx.x * 256 + threadIdx.x;
    int chunk = blockIdx.y;
    int i0    = chunk * CLEN;
    const float* zp = z  + (size_t)i0 * CH + ch;
    const float* xp = x  + (size_t)i0 * CH + ch;
    float*       op = x1 + (size_t)i0 * CH + ch;

    float P    = g_carry[chunk * CH + ch];
    float apow = powf(ALPHA_F, (float)(i0 + 1));       // a^{i0+1}
    float S    = ALPHA_F * (1.f - apow) / (1.f - ALPHA_F); // S_{i0+1}
#pragma unroll 4
    for (int t = 0; t < CLEN; t++) {
        float zv = zp[(size_t)t * CH];
        P = ALPHA_F * (P + zv);
        op[(size_t)t * CH] = xp[(size_t)t * CH] + P + (1.f - S) * zv;
        apow *= ALPHA_F;
        S += apow;
    }
}

// ---------------- launch -----------------------------------------------------
extern "C" void kernel_launch(void* const* d_in, const int* in_sizes, int n_in,
                              void* d_out, int out_size)
{
    const float* x     = (const float*)d_in[0];
    const float* w_lin = (const float*)d_in[1];
    const float* b_lin = (const float*)d_in[2];
    const float* w1    = (const float*)d_in[3];
    const float* b1    = (const float*)d_in[4];
    const float* w2    = (const float*)d_in[5];
    const float* b2    = (const float*)d_in[6];
    const float* g1    = (const float*)d_in[7];
    const float* be1   = (const float*)d_in[8];
    const float* g2    = (const float*)d_in[9];
    const float* be2   = (const float*)d_in[10];
    float* out = (float*)d_out;

    float *py, *pz, *px1, *ph;
    cudaGetSymbolAddress((void**)&py,  g_y);
    cudaGetSymbolAddress((void**)&pz,  g_z);
    cudaGetSymbolAddress((void**)&px1, g_x1);
    cudaGetSymbolAddress((void**)&ph,  g_h);

    // 1) y1 = LN(x; g1, be1)
    ln_kernel<<<MTOT / 8, 256>>>(x, g1, be1, py);

    // 2) z = y1 * w_lin^T + b_lin   (M=32768, N=512, K=512)
    gemm_tf32<false, false><<<dim3(DMODEL / BN, MTOT / BM), 256>>>(
        py, w_lin, b_lin, nullptr, pz, MTOT, DMODEL, DMODEL);

    // 3) x1 = x + W*z  via chunked linear scan
    scan_pass1<<<dim3(CH / 256, NCHUNK), 256>>>(pz);
    scan_pass2<<<CH / 256, 256>>>();
    scan_pass3<<<dim3(CH / 256, NCHUNK), 256>>>(x, pz, px1);

    // 4) y2 = LN(x1; g2, be2)
    ln_kernel<<<MTOT / 8, 256>>>(px1, g2, be2, py);

    // 5) h = relu(y2 * w1^T + b1)   (N=2048, K=512)
    gemm_tf32<true, false><<<dim3(FFDIM / BN, MTOT / BM), 256>>>(
        py, w1, b1, nullptr, ph, MTOT, FFDIM, DMODEL);

    // 6) out = x1 + h * w2^T + b2   (N=512, K=2048)
    gemm_tf32<false, true><<<dim3(DMODEL / BN, MTOT / BM), 256>>>(
        ph, w2, b2, px1, out, MTOT, DMODEL, FFDIM);
}

// round 2
// speedup vs baseline: 1.3664x; 1.3664x over previous
#include <cuda_runtime.h>
#include <cuda_bf16.h>
#include <cstdint>
#include <cstdio>

// Problem constants
#define SEQ     2048
#define BATCH   16
#define DMODEL  512
#define FFDIM   2048
#define MTOT    (SEQ*BATCH)          // 32768 token rows
#define CH      (BATCH*DMODEL)       // 8192 channels for the scan
#define ALPHA_F 0.9f
#define EPS_F   1e-5f

// Scan chunking
#define NCHUNK  16
#define CLEN    (SEQ/NCHUNK)         // 128

// ---------------- scratch (static device globals; no allocation) ------------
__device__ float g_y [(size_t)MTOT*DMODEL];   // LN output (reused for y1,y2)
__device__ float g_z [(size_t)MTOT*DMODEL];   // projection output
__device__ float g_x1[(size_t)MTOT*DMODEL];   // x + attn
__device__ float g_h [(size_t)MTOT*FFDIM];    // relu(ffn hidden)
__device__ float g_E [NCHUNK*CH];             // chunk-local scan end values
__device__ float g_carry[NCHUNK*CH];          // inter-chunk carries

// ---------------- helpers ----------------------------------------------------
__device__ __forceinline__ void mma_tf32(float* c, const uint32_t* a, const uint32_t* b) {
    asm volatile(
        "mma.sync.aligned.m16n8k8.row.col.f32.tf32.tf32.f32 "
        "{%0,%1,%2,%3},{%4,%5,%6,%7},{%8,%9},{%0,%1,%2,%3};\n"
        : "+f"(c[0]), "+f"(c[1]), "+f"(c[2]), "+f"(c[3])
        : "r"(a[0]), "r"(a[1]), "r"(a[2]), "r"(a[3]),
          "r"(b[0]), "r"(b[1]));
}

__device__ __forceinline__ void cp_async16(uint32_t smem_addr, const void* gptr) {
    asm volatile("cp.async.cg.shared.global [%0], [%1], 16;\n"
                 :: "r"(smem_addr), "l"(gptr));
}

// ---------------- LayerNorm: one warp per row of 512 -------------------------
__global__ __launch_bounds__(256) void ln_kernel(
    const float* __restrict__ x, const float* __restrict__ gamma,
    const float* __restrict__ beta, float* __restrict__ y)
{
    int row  = blockIdx.x * 8 + (threadIdx.x >> 5);
    int lane = threadIdx.x & 31;
    const float4* xr = reinterpret_cast<const float4*>(x + (size_t)row * DMODEL);
    const float4* g4 = reinterpret_cast<const float4*>(gamma);
    const float4* b4 = reinterpret_cast<const float4*>(beta);
    float4* yr = reinterpret_cast<float4*>(y + (size_t)row * DMODEL);

    float4 v[4];
    float sum = 0.f, sq = 0.f;
#pragma unroll
    for (int i = 0; i < 4; i++) {
        v[i] = xr[lane + i * 32];
        sum += v[i].x + v[i].y + v[i].z + v[i].w;
        sq  += v[i].x*v[i].x + v[i].y*v[i].y + v[i].z*v[i].z + v[i].w*v[i].w;
    }
#pragma unroll
    for (int o = 16; o; o >>= 1) {
        sum += __shfl_xor_sync(0xffffffffu, sum, o);
        sq  += __shfl_xor_sync(0xffffffffu, sq,  o);
    }
    float m    = sum * (1.f / DMODEL);
    float var  = sq * (1.f / DMODEL) - m * m;
    float rstd = rsqrtf(var + EPS_F);
#pragma unroll
    for (int i = 0; i < 4; i++) {
        float4 gv = g4[lane + i * 32];
        float4 bv = b4[lane + i * 32];
        float4 o;
        o.x = (v[i].x - m) * rstd * gv.x + bv.x;
        o.y = (v[i].y - m) * rstd * gv.y + bv.y;
        o.z = (v[i].z - m) * rstd * gv.z + bv.z;
        o.w = (v[i].w - m) * rstd * gv.w + bv.w;
        yr[lane + i * 32] = o;
    }
}

// ---------------- tf32 tensor-core GEMM v2: pipelined cp.async ---------------
// C = act(A*B^T + bias) [+ res].  A: [M,K] row-major fp32. B: [N,K] row-major.
// BM=128, BN=128, BK=32, 3-stage cp.async pipeline, 256 threads = 8 warps
// (2 m-halves x 4 n-quarters), warp tile 64x32. f32 bits consumed as tf32.
#define BM 128
#define BN 128
#define BK 32
#define NSTG 3
#define APITCH 36                      // 32 + 4 pad (words)
#define STAGE_WORDS (2 * BM * APITCH)  // A half + B half per stage (9216 words)
#define GEMM_SMEM_BYTES (NSTG * STAGE_WORDS * 4)  // 110592

template<bool RELU, bool RES>
__global__ __launch_bounds__(256, 2) void gemm_tf32(
    const float* __restrict__ A, const float* __restrict__ B,
    const float* __restrict__ bias, const float* __restrict__ res,
    float* __restrict__ C, int M, int N, int K)
{
    extern __shared__ uint32_t sm[];

    const int tid  = threadIdx.x;
    const int warp = tid >> 5;
    const int lane = tid & 31;
    const int wm   = warp >> 2;    // 0..1  (m half, 64 rows)
    const int wn   = warp & 3;     // 0..3  (n quarter, 32 cols)
    const int g    = lane >> 2;    // 0..7
    const int tg   = lane & 3;     // 0..3

    const int m0 = blockIdx.y * BM;
    const int n0 = blockIdx.x * BN;

    const int lr = tid >> 3;        // load row base (0..31)
    const int lc = (tid & 7) * 4;   // load col within BK

    const int nk = K / BK;

    float acc[4][4][4];
#pragma unroll
    for (int mt = 0; mt < 4; mt++)
#pragma unroll
        for (int nt = 0; nt < 4; nt++)
#pragma unroll
            for (int i = 0; i < 4; i++) acc[mt][nt][i] = 0.f;

#define AS(s, r, c) sm[(s) * STAGE_WORDS + (r) * APITCH + (c)]
#define BS(s, r, c) sm[(s) * STAGE_WORDS + BM * APITCH + (r) * APITCH + (c)]

    const float* Ag = A + (size_t)(m0 + lr) * K + lc;
    const float* Bg = B + (size_t)(n0 + lr) * K + lc;

    // prologue: fill stages 0..NSTG-2
#pragma unroll
    for (int s = 0; s < NSTG - 1; s++) {
#pragma unroll
        for (int r = 0; r < 4; r++) {
            cp_async16((uint32_t)__cvta_generic_to_shared(&AS(s, lr + 32 * r, lc)),
                       Ag + (size_t)32 * r * K + s * BK);
            cp_async16((uint32_t)__cvta_generic_to_shared(&BS(s, lr + 32 * r, lc)),
                       Bg + (size_t)32 * r * K + s * BK);
        }
        asm volatile("cp.async.commit_group;\n");
    }

    for (int k = 0; k < nk; k++) {
        asm volatile("cp.async.wait_group %0;\n" :: "n"(NSTG - 2));
        __syncthreads();

        // issue next stage (slot was fully consumed at iteration k-1)
        int kn = k + NSTG - 1;
        if (kn < nk) {
            int sn = kn % NSTG;
#pragma unroll
            for (int r = 0; r < 4; r++) {
                cp_async16((uint32_t)__cvta_generic_to_shared(&AS(sn, lr + 32 * r, lc)),
                           Ag + (size_t)32 * r * K + kn * BK);
                cp_async16((uint32_t)__cvta_generic_to_shared(&BS(sn, lr + 32 * r, lc)),
                           Bg + (size_t)32 * r * K + kn * BK);
            }
        }
        asm volatile("cp.async.commit_group;\n");   // (possibly empty) keeps group count fixed

        const int s = k % NSTG;
#pragma unroll
        for (int kk = 0; kk < 4; kk++) {
            uint32_t af[4][4], bf[4][2];
#pragma unroll
            for (int mt = 0; mt < 4; mt++) {
                int mr = wm * 64 + mt * 16;
                af[mt][0] = AS(s, mr + g,     kk * 8 + tg);
                af[mt][1] = AS(s, mr + g + 8, kk * 8 + tg);
                af[mt][2] = AS(s, mr + g,     kk * 8 + tg + 4);
                af[mt][3] = AS(s, mr + g + 8, kk * 8 + tg + 4);
            }
#pragma unroll
            for (int nt = 0; nt < 4; nt++) {
                int nr = wn * 32 + nt * 8;
                bf[nt][0] = BS(s, nr + g, kk * 8 + tg);
                bf[nt][1] = BS(s, nr + g, kk * 8 + tg + 4);
            }
#pragma unroll
            for (int mt = 0; mt < 4; mt++)
#pragma unroll
                for (int nt = 0; nt < 4; nt++)
                    mma_tf32(acc[mt][nt], af[mt], bf[nt]);
        }
    }

    // epilogue: bias (+relu) (+residual)
#pragma unroll
    for (int mt = 0; mt < 4; mt++) {
        int r0 = m0 + wm * 64 + mt * 16 + g;
#pragma unroll
        for (int nt = 0; nt < 4; nt++) {
            int cc = n0 + wn * 32 + nt * 8 + tg * 2;
            float bv0 = bias[cc], bv1 = bias[cc + 1];
            float v0 = acc[mt][nt][0] + bv0;
            float v1 = acc[mt][nt][1] + bv1;
            float v2 = acc[mt][nt][2] + bv0;
            float v3 = acc[mt][nt][3] + bv1;
            if (RELU) {
                v0 = fmaxf(v0, 0.f); v1 = fmaxf(v1, 0.f);
                v2 = fmaxf(v2, 0.f); v3 = fmaxf(v3, 0.f);
            }
            if (RES) {
                const float* r1 = res + (size_t)r0 * N + cc;
                const float* r2 = res + (size_t)(r0 + 8) * N + cc;
                v0 += r1[0]; v1 += r1[1];
                v2 += r2[0]; v3 += r2[1];
            }
            *reinterpret_cast<float2*>(&C[(size_t)r0 * N + cc])       = make_float2(v0, v1);
            *reinterpret_cast<float2*>(&C[(size_t)(r0 + 8) * N + cc]) = make_float2(v2, v3);
        }
    }
#undef AS
#undef BS
}

// ---------------- causal exp-decay mixing as a chunked linear scan -----------
// attn_i = P_i + (1 - S_{i+1}) z_i,  P_i = a(P_{i-1} + z_i),  S_{i+1}=sum_{k=1}^{i+1} a^k
__global__ __launch_bounds__(256) void scan_pass1(const float* __restrict__ z)
{
    int ch    = blockIdx.x * 256 + threadIdx.x;   // 0..CH-1
    int chunk = blockIdx.y;
    const float* zp = z + (size_t)chunk * CLEN * CH + ch;
    float P = 0.f;
#pragma unroll 4
    for (int t = 0; t < CLEN; t++)
        P = ALPHA_F * (P + zp[(size_t)t * CH]);
    g_E[chunk * CH + ch] = P;
}

__global__ __launch_bounds__(256) void scan_pass2()
{
    int ch = blockIdx.x * 256 + threadIdx.x;
    float aL = powf(ALPHA_F, (float)CLEN);
    float carry = 0.f;
#pragma unroll
    for (int c = 0; c < NCHUNK; c++) {
        g_carry[c * CH + ch] = carry;
        carry = g_E[c * CH + ch] + aL * carry;
    }
}

__global__ __launch_bounds__(256) void scan_pass3(
    const float* __restrict__ x, const float* __restrict__ z, float* __restrict__ x1)
{
    int ch    = blockIdx.x * 256 + threadIdx.x;
    int chunk = blockIdx.y;
    int i0    = chunk * CLEN;
    const float* zp = z  + (size_t)i0 * CH + ch;
    const float* xp = x  + (size_t)i0 * CH + ch;
    float*       op = x1 + (size_t)i0 * CH + ch;

    float P    = g_carry[chunk * CH + ch];
    float apow = powf(ALPHA_F, (float)(i0 + 1));           // a^{i0+1}
    float S    = ALPHA_F * (1.f - apow) / (1.f - ALPHA_F); // S_{i0+1}
#pragma unroll 4
    for (int t = 0; t < CLEN; t++) {
        float zv = zp[(size_t)t * CH];
        P = ALPHA_F * (P + zv);
        op[(size_t)t * CH] = xp[(size_t)t * CH] + P + (1.f - S) * zv;
        apow *= ALPHA_F;
        S += apow;
    }
}

// ---------------- launch -----------------------------------------------------
extern "C" void kernel_launch(void* const* d_in, const int* in_sizes, int n_in,
                              void* d_out, int out_size)
{
    const float* x     = (const float*)d_in[0];
    const float* w_lin = (const float*)d_in[1];
    const float* b_lin = (const float*)d_in[2];
    const float* w1    = (const float*)d_in[3];
    const float* b1    = (const float*)d_in[4];
    const float* w2    = (const float*)d_in[5];
    const float* b2    = (const float*)d_in[6];
    const float* g1    = (const float*)d_in[7];
    const float* be1   = (const float*)d_in[8];
    const float* g2    = (const float*)d_in[9];
    const float* be2   = (const float*)d_in[10];
    float* out = (float*)d_out;

    float *py, *pz, *px1, *ph;
    cudaGetSymbolAddress((void**)&py,  g_y);
    cudaGetSymbolAddress((void**)&pz,  g_z);
    cudaGetSymbolAddress((void**)&px1, g_x1);
    cudaGetSymbolAddress((void**)&ph,  g_h);

    // allow >48KB dynamic smem (idempotent; executes immediately even under capture)
    cudaFuncSetAttribute(gemm_tf32<false, false>,
                         cudaFuncAttributeMaxDynamicSharedMemorySize, GEMM_SMEM_BYTES);
    cudaFuncSetAttribute(gemm_tf32<true, false>,
                         cudaFuncAttributeMaxDynamicSharedMemorySize, GEMM_SMEM_BYTES);
    cudaFuncSetAttribute(gemm_tf32<false, true>,
                         cudaFuncAttributeMaxDynamicSharedMemorySize, GEMM_SMEM_BYTES);

    // 1) y1 = LN(x; g1, be1)
    ln_kernel<<<MTOT / 8, 256>>>(x, g1, be1, py);

    // 2) z = y1 * w_lin^T + b_lin   (M=32768, N=512, K=512)
    gemm_tf32<false, false><<<dim3(DMODEL / BN, MTOT / BM), 256, GEMM_SMEM_BYTES>>>(
        py, w_lin, b_lin, nullptr, pz, MTOT, DMODEL, DMODEL);

    // 3) x1 = x + W*z  via chunked linear scan
    scan_pass1<<<dim3(CH / 256, NCHUNK), 256>>>(pz);
    scan_pass2<<<CH / 256, 256>>>();
    scan_pass3<<<dim3(CH / 256, NCHUNK), 256>>>(x, pz, px1);

    // 4) y2 = LN(x1; g2, be2)
    ln_kernel<<<MTOT / 8, 256>>>(px1, g2, be2, py);

    // 5) h = relu(y2 * w1^T + b1)   (N=2048, K=512)
    gemm_tf32<true, false><<<dim3(FFDIM / BN, MTOT / BM), 256, GEMM_SMEM_BYTES>>>(
        py, w1, b1, nullptr, ph, MTOT, FFDIM, DMODEL);

    // 6) out = x1 + h * w2^T + b2   (N=512, K=2048)
    gemm_tf32<false, true><<<dim3(DMODEL / BN, MTOT / BM), 256, GEMM_SMEM_BYTES>>>(
        ph, w2, b2, px1, out, MTOT, DMODEL, FFDIM);
}